// round 2
// baseline (speedup 1.0000x reference)
#include <cuda_runtime.h>
#include <cuda_bf16.h>
#include <math.h>

// Problem constants
#define S_LEN 2048
#define H_DIM 2048
#define NH    16
#define NKV   4
#define HD    128          // head dim
#define EPS_F 1.1920928955078125e-07f

// ---------------------------------------------------------------------------
// Scratch buffers (device globals; no allocation allowed)
// ---------------------------------------------------------------------------
__device__ float g_qproj[S_LEN * H_DIM];        // [S, NH*D]   16 MB
__device__ float g_q[NH * S_LEN * HD];          // [NH, S, D]  16 MB (normed+roped)
__device__ float g_kproj[S_LEN * NKV * HD];     // [S, NKV*D]   4 MB
__device__ float g_k[NKV * S_LEN * HD];         // [NKV, S, D]  4 MB
__device__ float g_v[S_LEN * NKV * HD];         // [S, NKV*D]   4 MB (no transform)
__device__ float g_attn[S_LEN * H_DIM];         // [S, NH*D]   16 MB

// ---------------------------------------------------------------------------
// SGEMM: C[M,N] = A[M,K] * B[N,K]^T  (both row-major). M,N,K multiples of 128/8.
// 128x128 tile, BK=8, 256 threads, 8x8 per thread.
// ---------------------------------------------------------------------------
__global__ __launch_bounds__(256) void sgemm_nt_kernel(
    const float* __restrict__ A, const float* __restrict__ B,
    float* __restrict__ C, int M, int N, int K)
{
    __shared__ float As[8][128];
    __shared__ float Bs[8][128];

    const int tid = threadIdx.x;
    const int bm = blockIdx.y * 128;
    const int bn = blockIdx.x * 128;
    const int ty = tid >> 4;      // 0..15
    const int tx = tid & 15;      // 0..15

    const int lrow = tid >> 1;          // 0..127
    const int lcol = (tid & 1) * 4;     // 0 or 4

    const float* Ap = A + (size_t)(bm + lrow) * K + lcol;
    const float* Bp = B + (size_t)(bn + lrow) * K + lcol;

    float acc[8][8];
#pragma unroll
    for (int i = 0; i < 8; i++)
#pragma unroll
        for (int j = 0; j < 8; j++) acc[i][j] = 0.0f;

    for (int k0 = 0; k0 < K; k0 += 8) {
        float4 av = *(const float4*)(Ap + k0);
        float4 bv = *(const float4*)(Bp + k0);
        As[lcol + 0][lrow] = av.x; As[lcol + 1][lrow] = av.y;
        As[lcol + 2][lrow] = av.z; As[lcol + 3][lrow] = av.w;
        Bs[lcol + 0][lrow] = bv.x; Bs[lcol + 1][lrow] = bv.y;
        Bs[lcol + 2][lrow] = bv.z; Bs[lcol + 3][lrow] = bv.w;
        __syncthreads();

#pragma unroll
        for (int kk = 0; kk < 8; kk++) {
            float4 a0 = *(const float4*)&As[kk][ty * 8];
            float4 a1 = *(const float4*)&As[kk][ty * 8 + 4];
            float4 b0 = *(const float4*)&Bs[kk][tx * 8];
            float4 b1 = *(const float4*)&Bs[kk][tx * 8 + 4];
            float ra[8] = {a0.x, a0.y, a0.z, a0.w, a1.x, a1.y, a1.z, a1.w};
            float rb[8] = {b0.x, b0.y, b0.z, b0.w, b1.x, b1.y, b1.z, b1.w};
#pragma unroll
            for (int i = 0; i < 8; i++)
#pragma unroll
                for (int j = 0; j < 8; j++)
                    acc[i][j] = fmaf(ra[i], rb[j], acc[i][j]);
        }
        __syncthreads();
    }

#pragma unroll
    for (int i = 0; i < 8; i++) {
        float* cp = C + (size_t)(bm + ty * 8 + i) * N + bn + tx * 8;
        float4 c0 = make_float4(acc[i][0], acc[i][1], acc[i][2], acc[i][3]);
        float4 c1 = make_float4(acc[i][4], acc[i][5], acc[i][6], acc[i][7]);
        *(float4*)(cp) = c0;
        *(float4*)(cp + 4) = c1;
    }
}

// ---------------------------------------------------------------------------
// Fused per-head RMSNorm + RoPE. One warp per (s, head) row of D=128.
// in:  [S, nheads*128] ; out: [nheads, S, 128]
// ---------------------------------------------------------------------------
__global__ __launch_bounds__(256) void norm_rope_kernel(
    const float* __restrict__ in, const float* __restrict__ sinp,
    const float* __restrict__ cosp, const float* __restrict__ w,
    float* __restrict__ out, int nheads, int nrows)
{
    int warp = (blockIdx.x * blockDim.x + threadIdx.x) >> 5;
    int lane = threadIdx.x & 31;
    if (warp >= nrows) return;
    int s = warp / nheads;
    int h = warp - s * nheads;

    const float* xp = in + (size_t)s * (nheads * HD) + h * HD;
    float x0 = xp[lane];
    float x1 = xp[lane + 32];
    float x2 = xp[lane + 64];
    float x3 = xp[lane + 96];

    float ss = x0 * x0 + x1 * x1 + x2 * x2 + x3 * x3;
#pragma unroll
    for (int o = 16; o; o >>= 1) ss += __shfl_xor_sync(0xffffffffu, ss, o);
    float r = rsqrtf(ss * (1.0f / 128.0f) + EPS_F);

    x0 *= r * w[lane];
    x1 *= r * w[lane + 32];
    x2 *= r * w[lane + 64];
    x3 *= r * w[lane + 96];

    const float* sp = sinp + (size_t)s * HD;
    const float* cp = cosp + (size_t)s * HD;
    // d < 64:  out = cos*x - sin*x[d+64];  d >= 64: out = cos*x + sin*x[d-64]
    float o0 = cp[lane]      * x0 - sp[lane]      * x2;
    float o1 = cp[lane + 32] * x1 - sp[lane + 32] * x3;
    float o2 = cp[lane + 64] * x2 + sp[lane + 64] * x0;
    float o3 = cp[lane + 96] * x3 + sp[lane + 96] * x1;

    float* op = out + ((size_t)h * S_LEN + s) * HD;
    op[lane]      = o0;
    op[lane + 32] = o1;
    op[lane + 64] = o2;
    op[lane + 96] = o3;
}

// ---------------------------------------------------------------------------
// Causal flash attention, fp32.
// Q: [NH, S, D]   K: [NKV, S, D]   V: [S, NKV*D]   O: [S, NH*D]
// CTA = (qblock of 64, head). 256 threads, thread (ty,tx) 16x16 owns
// 4 q-rows x 4 k-cols for S, and 4 q-rows x 8 d-cols for O.
// ---------------------------------------------------------------------------
#define QS_STRIDE 132
#define PS_STRIDE 68
#define ATTN_SMEM_FLOATS (64 * QS_STRIDE * 3 + 64 * PS_STRIDE)

__global__ __launch_bounds__(256) void attn_kernel(
    const float* __restrict__ Q, const float* __restrict__ Kn,
    const float* __restrict__ V, float* __restrict__ O)
{
    extern __shared__ float sm[];
    float* Qs = sm;                       // [64][132]
    float* Ks = Qs + 64 * QS_STRIDE;      // [64][132]
    float* Vs = Ks + 64 * QS_STRIDE;      // [64][132]
    float* Ps = Vs + 64 * QS_STRIDE;      // [64][68]

    const int h  = blockIdx.y;
    const int qb = blockIdx.x;
    const int kvh = h >> 2;
    const int tid = threadIdx.x;
    const int ty = tid >> 4;
    const int tx = tid & 15;
    const int q0 = qb * 64;
    const float scale = 0.08838834764831845f;  // 1/sqrt(128)

    // Load Q tile
    const float* qptr = Q + ((size_t)h * S_LEN + q0) * HD;
    for (int i = tid; i < 64 * 32; i += 256) {
        int r = i >> 5, c = (i & 31) << 2;
        float4 v4 = *(const float4*)(qptr + r * HD + c);
        float* d = &Qs[r * QS_STRIDE + c];
        d[0] = v4.x; d[1] = v4.y; d[2] = v4.z; d[3] = v4.w;
    }

    float acc[4][8];
    float m_i[4], l_i[4];
#pragma unroll
    for (int i = 0; i < 4; i++) {
        m_i[i] = -INFINITY; l_i[i] = 0.0f;
#pragma unroll
        for (int j = 0; j < 8; j++) acc[i][j] = 0.0f;
    }

    for (int kb = 0; kb <= qb; kb++) {
        __syncthreads();   // previous iter done reading Ks/Vs/Ps
        const int k0 = kb * 64;
        const float* kptr = Kn + ((size_t)kvh * S_LEN + k0) * HD;
        const float* vptr = V + (size_t)k0 * (NKV * HD) + kvh * HD;
        for (int i = tid; i < 64 * 32; i += 256) {
            int r = i >> 5, c = (i & 31) << 2;
            float4 kv4 = *(const float4*)(kptr + r * HD + c);
            float* kd = &Ks[r * QS_STRIDE + c];
            kd[0] = kv4.x; kd[1] = kv4.y; kd[2] = kv4.z; kd[3] = kv4.w;
            float4 vv4 = *(const float4*)(vptr + (size_t)r * (NKV * HD) + c);
            float* vd = &Vs[r * QS_STRIDE + c];
            vd[0] = vv4.x; vd[1] = vv4.y; vd[2] = vv4.z; vd[3] = vv4.w;
        }
        __syncthreads();

        // S = Q K^T  (4x4 per thread)
        float s[4][4];
#pragma unroll
        for (int i = 0; i < 4; i++)
#pragma unroll
            for (int j = 0; j < 4; j++) s[i][j] = 0.0f;

        for (int d = 0; d < HD; d += 4) {
            float4 qv[4], kv[4];
#pragma unroll
            for (int i = 0; i < 4; i++)
                qv[i] = *(const float4*)&Qs[(4 * ty + i) * QS_STRIDE + d];
#pragma unroll
            for (int j = 0; j < 4; j++)
                kv[j] = *(const float4*)&Ks[(4 * tx + j) * QS_STRIDE + d];
#pragma unroll
            for (int i = 0; i < 4; i++)
#pragma unroll
                for (int j = 0; j < 4; j++) {
                    s[i][j] = fmaf(qv[i].x, kv[j].x, s[i][j]);
                    s[i][j] = fmaf(qv[i].y, kv[j].y, s[i][j]);
                    s[i][j] = fmaf(qv[i].z, kv[j].z, s[i][j]);
                    s[i][j] = fmaf(qv[i].w, kv[j].w, s[i][j]);
                }
        }

        const bool diag = (kb == qb);
#pragma unroll
        for (int i = 0; i < 4; i++) {
#pragma unroll
            for (int j = 0; j < 4; j++) {
                s[i][j] *= scale;
                if (diag && (4 * tx + j > 4 * ty + i)) s[i][j] = -INFINITY;
            }
        }

        // Online softmax per q-row (reduce across the 16 tx lanes of this warp half)
#pragma unroll
        for (int i = 0; i < 4; i++) {
            float rm = fmaxf(fmaxf(s[i][0], s[i][1]), fmaxf(s[i][2], s[i][3]));
#pragma unroll
            for (int o = 8; o; o >>= 1)
                rm = fmaxf(rm, __shfl_xor_sync(0xffffffffu, rm, o));
            float mnew = fmaxf(m_i[i], rm);
            float corr = __expf(m_i[i] - mnew);
            float rs = 0.0f;
#pragma unroll
            for (int j = 0; j < 4; j++) {
                s[i][j] = __expf(s[i][j] - mnew);
                rs += s[i][j];
            }
#pragma unroll
            for (int o = 8; o; o >>= 1)
                rs += __shfl_xor_sync(0xffffffffu, rs, o);
            l_i[i] = l_i[i] * corr + rs;
            m_i[i] = mnew;
#pragma unroll
            for (int j = 0; j < 8; j++) acc[i][j] *= corr;
#pragma unroll
            for (int j = 0; j < 4; j++)
                Ps[(4 * ty + i) * PS_STRIDE + 4 * tx + j] = s[i][j];
        }
        __syncthreads();

        // O += P * V
#pragma unroll 4
        for (int kk = 0; kk < 64; kk++) {
            float4 v0 = *(const float4*)&Vs[kk * QS_STRIDE + 8 * tx];
            float4 v1 = *(const float4*)&Vs[kk * QS_STRIDE + 8 * tx + 4];
#pragma unroll
            for (int i = 0; i < 4; i++) {
                float p = Ps[(4 * ty + i) * PS_STRIDE + kk];
                acc[i][0] = fmaf(p, v0.x, acc[i][0]);
                acc[i][1] = fmaf(p, v0.y, acc[i][1]);
                acc[i][2] = fmaf(p, v0.z, acc[i][2]);
                acc[i][3] = fmaf(p, v0.w, acc[i][3]);
                acc[i][4] = fmaf(p, v1.x, acc[i][4]);
                acc[i][5] = fmaf(p, v1.y, acc[i][5]);
                acc[i][6] = fmaf(p, v1.z, acc[i][6]);
                acc[i][7] = fmaf(p, v1.w, acc[i][7]);
            }
        }
    }

    // Epilogue: normalize and store to [S, NH*D]
#pragma unroll
    for (int i = 0; i < 4; i++) {
        float inv = 1.0f / l_i[i];
        int qrow = q0 + 4 * ty + i;
        float* optr = O + (size_t)qrow * H_DIM + h * HD + 8 * tx;
        float4 c0 = make_float4(acc[i][0] * inv, acc[i][1] * inv,
                                acc[i][2] * inv, acc[i][3] * inv);
        float4 c1 = make_float4(acc[i][4] * inv, acc[i][5] * inv,
                                acc[i][6] * inv, acc[i][7] * inv);
        *(float4*)(optr) = c0;
        *(float4*)(optr + 4) = c1;
    }
}

// ---------------------------------------------------------------------------
// Launch
// Inputs (metadata order): x, sin, cos, mask, wq, wk, wv, wo, q_norm_w, k_norm_w
// ---------------------------------------------------------------------------
extern "C" void kernel_launch(void* const* d_in, const int* in_sizes, int n_in,
                              void* d_out, int out_size)
{
    const float* x    = (const float*)d_in[0];
    const float* sinp = (const float*)d_in[1];
    const float* cosp = (const float*)d_in[2];
    // d_in[3] = mask (ignored; causal structure is known)
    const float* wq   = (const float*)d_in[4];
    const float* wk   = (const float*)d_in[5];
    const float* wv   = (const float*)d_in[6];
    const float* wo   = (const float*)d_in[7];
    const float* qnw  = (const float*)d_in[8];
    const float* knw  = (const float*)d_in[9];
    float* out = (float*)d_out;

    float *qproj, *q, *kproj, *k, *v, *attn;
    cudaGetSymbolAddress((void**)&qproj, g_qproj);
    cudaGetSymbolAddress((void**)&q,     g_q);
    cudaGetSymbolAddress((void**)&kproj, g_kproj);
    cudaGetSymbolAddress((void**)&k,     g_k);
    cudaGetSymbolAddress((void**)&v,     g_v);
    cudaGetSymbolAddress((void**)&attn,  g_attn);

    // 1) projections
    sgemm_nt_kernel<<<dim3(H_DIM / 128, S_LEN / 128), 256>>>(x, wq, qproj, S_LEN, H_DIM, H_DIM);
    sgemm_nt_kernel<<<dim3(NKV * HD / 128, S_LEN / 128), 256>>>(x, wk, kproj, S_LEN, NKV * HD, H_DIM);
    sgemm_nt_kernel<<<dim3(NKV * HD / 128, S_LEN / 128), 256>>>(x, wv, v, S_LEN, NKV * HD, H_DIM);

    // 2) rmsnorm + rope  (GQA: norm/rope the 4 kv heads once)
    {
        int qrows = S_LEN * NH;   // 32768 warps
        int krows = S_LEN * NKV;  //  8192 warps
        norm_rope_kernel<<<(qrows * 32 + 255) / 256, 256>>>(qproj, sinp, cosp, qnw, q, NH, qrows);
        norm_rope_kernel<<<(krows * 32 + 255) / 256, 256>>>(kproj, sinp, cosp, knw, k, NKV, krows);
    }

    // 3) causal flash attention
    {
        size_t smem = ATTN_SMEM_FLOATS * sizeof(float);  // ~116 KB
        cudaFuncSetAttribute(attn_kernel, cudaFuncAttributeMaxDynamicSharedMemorySize, (int)smem);
        attn_kernel<<<dim3(S_LEN / 64, NH), 256, smem>>>(q, k, v, attn);
    }

    // 4) output projection
    sgemm_nt_kernel<<<dim3(H_DIM / 128, S_LEN / 128), 256>>>(attn, wo, out, S_LEN, H_DIM, H_DIM);
}

// round 7
// speedup vs baseline: 1.3180x; 1.3180x over previous
#include <cuda_runtime.h>
#include <cuda_bf16.h>
#include <cstdint>
#include <math.h>

// Problem constants
#define S_LEN 2048
#define H_DIM 2048
#define NH    16
#define NKV   4
#define HD    128          // head dim
#define EPS_F 1.1920928955078125e-07f

// ---------------------------------------------------------------------------
// Scratch buffers (device globals; no allocation allowed)
// ---------------------------------------------------------------------------
__device__ float g_qproj[S_LEN * H_DIM];        // [S, NH*D]   16 MB
__device__ float g_q[NH * S_LEN * HD];          // [NH, S, D]  16 MB (normed+roped)
__device__ float g_kproj[S_LEN * NKV * HD];     // [S, NKV*D]   4 MB
__device__ float g_k[NKV * S_LEN * HD];         // [NKV, S, D]  4 MB
__device__ float g_v[S_LEN * NKV * HD];         // [S, NKV*D]   4 MB (no transform)
__device__ float g_attn[S_LEN * H_DIM];         // [S, NH*D]   16 MB

// ---------------------------------------------------------------------------
// TF32 helpers
// ---------------------------------------------------------------------------
__device__ __forceinline__ float tf32r(float x) {
    uint32_t u;
    asm("cvt.rna.tf32.f32 %0, %1;" : "=r"(u) : "f"(x));
    return __uint_as_float(u);
}

__device__ __forceinline__ void mma_tf32(float* c, const uint32_t* a, const uint32_t* b) {
    asm volatile(
        "mma.sync.aligned.m16n8k8.row.col.f32.tf32.tf32.f32 "
        "{%0,%1,%2,%3}, {%4,%5,%6,%7}, {%8,%9}, {%0,%1,%2,%3};\n"
        : "+f"(c[0]), "+f"(c[1]), "+f"(c[2]), "+f"(c[3])
        : "r"(a[0]), "r"(a[1]), "r"(a[2]), "r"(a[3]), "r"(b[0]), "r"(b[1]));
}

// ---------------------------------------------------------------------------
// TF32 tensor-core GEMM: C[M,N] = A[M,K] * B[N,K]^T (both row-major).
// CTA tile 128x128, BK=32, 256 threads = 8 warps (2 m x 4 n), warp tile 64x32.
// Each warp: 4x4 grid of m16n8k8 mma fragments.
// ---------------------------------------------------------------------------
#define GK_STRIDE 33
__global__ __launch_bounds__(256) void gemm_tf32_nt(
    const float* __restrict__ A, const float* __restrict__ B,
    float* __restrict__ C, int M, int N, int K)
{
    __shared__ float As[128][GK_STRIDE];   // [m][k]
    __shared__ float Bs[128][GK_STRIDE];   // [n][k]

    const int tid  = threadIdx.x;
    const int warp = tid >> 5;
    const int lane = tid & 31;
    const int wm   = warp >> 2;          // 0..1
    const int wn   = warp & 3;           // 0..3
    const int bm   = blockIdx.y * 128;
    const int bn   = blockIdx.x * 128;

    const int lr = tid >> 1;             // 0..127 (tile row loaded by this thread)
    const int lc = (tid & 1) * 16;       // 0 or 16

    const float* Ap = A + (size_t)(bm + lr) * K + lc;
    const float* Bp = B + (size_t)(bn + lr) * K + lc;

    float c[4][4][4];
#pragma unroll
    for (int mt = 0; mt < 4; mt++)
#pragma unroll
        for (int nt = 0; nt < 4; nt++)
#pragma unroll
            for (int e = 0; e < 4; e++) c[mt][nt][e] = 0.0f;

    const int grp = lane >> 2;           // 0..7
    const int qk  = lane & 3;            // 0..3

    for (int k0 = 0; k0 < K; k0 += 32) {
#pragma unroll
        for (int j = 0; j < 4; j++) {
            float4 av = *(const float4*)(Ap + k0 + j * 4);
            float4 bv = *(const float4*)(Bp + k0 + j * 4);
            As[lr][lc + j * 4 + 0] = tf32r(av.x);
            As[lr][lc + j * 4 + 1] = tf32r(av.y);
            As[lr][lc + j * 4 + 2] = tf32r(av.z);
            As[lr][lc + j * 4 + 3] = tf32r(av.w);
            Bs[lr][lc + j * 4 + 0] = tf32r(bv.x);
            Bs[lr][lc + j * 4 + 1] = tf32r(bv.y);
            Bs[lr][lc + j * 4 + 2] = tf32r(bv.z);
            Bs[lr][lc + j * 4 + 3] = tf32r(bv.w);
        }
        __syncthreads();

#pragma unroll
        for (int kk = 0; kk < 4; kk++) {
            const int kx = kk * 8 + qk;
            uint32_t af[4][4], bf[4][2];
#pragma unroll
            for (int mt = 0; mt < 4; mt++) {
                const int r0 = wm * 64 + mt * 16 + grp;
                af[mt][0] = __float_as_uint(As[r0][kx]);
                af[mt][1] = __float_as_uint(As[r0 + 8][kx]);
                af[mt][2] = __float_as_uint(As[r0][kx + 4]);
                af[mt][3] = __float_as_uint(As[r0 + 8][kx + 4]);
            }
#pragma unroll
            for (int nt = 0; nt < 4; nt++) {
                const int n0 = wn * 32 + nt * 8 + grp;
                bf[nt][0] = __float_as_uint(Bs[n0][kx]);
                bf[nt][1] = __float_as_uint(Bs[n0][kx + 4]);
            }
#pragma unroll
            for (int mt = 0; mt < 4; mt++)
#pragma unroll
                for (int nt = 0; nt < 4; nt++)
                    mma_tf32(c[mt][nt], af[mt], bf[nt]);
        }
        __syncthreads();
    }

    // Epilogue
#pragma unroll
    for (int mt = 0; mt < 4; mt++) {
        const int r0 = bm + wm * 64 + mt * 16 + grp;
#pragma unroll
        for (int nt = 0; nt < 4; nt++) {
            const int col = bn + wn * 32 + nt * 8 + qk * 2;
            *(float2*)&C[(size_t)r0 * N + col]       = make_float2(c[mt][nt][0], c[mt][nt][1]);
            *(float2*)&C[(size_t)(r0 + 8) * N + col] = make_float2(c[mt][nt][2], c[mt][nt][3]);
        }
    }
}

// ---------------------------------------------------------------------------
// Fused per-head RMSNorm + RoPE. One warp per (s, head) row of D=128.
// in:  [S, nheads*128] ; out: [nheads, S, 128]
// ---------------------------------------------------------------------------
__global__ __launch_bounds__(256) void norm_rope_kernel(
    const float* __restrict__ in, const float* __restrict__ sinp,
    const float* __restrict__ cosp, const float* __restrict__ w,
    float* __restrict__ out, int nheads, int nrows)
{
    int warp = (blockIdx.x * blockDim.x + threadIdx.x) >> 5;
    int lane = threadIdx.x & 31;
    if (warp >= nrows) return;
    int s = warp / nheads;
    int h = warp - s * nheads;

    const float* xp = in + (size_t)s * (nheads * HD) + h * HD;
    float x0 = xp[lane];
    float x1 = xp[lane + 32];
    float x2 = xp[lane + 64];
    float x3 = xp[lane + 96];

    float ss = x0 * x0 + x1 * x1 + x2 * x2 + x3 * x3;
#pragma unroll
    for (int o = 16; o; o >>= 1) ss += __shfl_xor_sync(0xffffffffu, ss, o);
    float r = rsqrtf(ss * (1.0f / 128.0f) + EPS_F);

    x0 *= r * w[lane];
    x1 *= r * w[lane + 32];
    x2 *= r * w[lane + 64];
    x3 *= r * w[lane + 96];

    const float* sp = sinp + (size_t)s * HD;
    const float* cp = cosp + (size_t)s * HD;
    float o0 = cp[lane]      * x0 - sp[lane]      * x2;
    float o1 = cp[lane + 32] * x1 - sp[lane + 32] * x3;
    float o2 = cp[lane + 64] * x2 + sp[lane + 64] * x0;
    float o3 = cp[lane + 96] * x3 + sp[lane + 96] * x1;

    float* op = out + ((size_t)h * S_LEN + s) * HD;
    op[lane]      = o0;
    op[lane + 32] = o1;
    op[lane + 64] = o2;
    op[lane + 96] = o3;
}

// ---------------------------------------------------------------------------
// Causal flash attention, fp32.
// ---------------------------------------------------------------------------
#define QS_STRIDE 132
#define PS_STRIDE 68
#define ATTN_SMEM_FLOATS (64 * QS_STRIDE * 3 + 64 * PS_STRIDE)

__global__ __launch_bounds__(256) void attn_kernel(
    const float* __restrict__ Q, const float* __restrict__ Kn,
    const float* __restrict__ V, float* __restrict__ O)
{
    extern __shared__ float sm[];
    float* Qs = sm;
    float* Ks = Qs + 64 * QS_STRIDE;
    float* Vs = Ks + 64 * QS_STRIDE;
    float* Ps = Vs + 64 * QS_STRIDE;

    const int h  = blockIdx.y;
    const int qb = blockIdx.x;
    const int kvh = h >> 2;
    const int tid = threadIdx.x;
    const int ty = tid >> 4;
    const int tx = tid & 15;
    const int q0 = qb * 64;
    const float scale = 0.08838834764831845f;

    const float* qptr = Q + ((size_t)h * S_LEN + q0) * HD;
    for (int i = tid; i < 64 * 32; i += 256) {
        int r = i >> 5, c = (i & 31) << 2;
        float4 v4 = *(const float4*)(qptr + r * HD + c);
        float* d = &Qs[r * QS_STRIDE + c];
        d[0] = v4.x; d[1] = v4.y; d[2] = v4.z; d[3] = v4.w;
    }

    float acc[4][8];
    float m_i[4], l_i[4];
#pragma unroll
    for (int i = 0; i < 4; i++) {
        m_i[i] = -INFINITY; l_i[i] = 0.0f;
#pragma unroll
        for (int j = 0; j < 8; j++) acc[i][j] = 0.0f;
    }

    for (int kb = 0; kb <= qb; kb++) {
        __syncthreads();
        const int k0 = kb * 64;
        const float* kptr = Kn + ((size_t)kvh * S_LEN + k0) * HD;
        const float* vptr = V + (size_t)k0 * (NKV * HD) + kvh * HD;
        for (int i = tid; i < 64 * 32; i += 256) {
            int r = i >> 5, c = (i & 31) << 2;
            float4 kv4 = *(const float4*)(kptr + r * HD + c);
            float* kd = &Ks[r * QS_STRIDE + c];
            kd[0] = kv4.x; kd[1] = kv4.y; kd[2] = kv4.z; kd[3] = kv4.w;
            float4 vv4 = *(const float4*)(vptr + (size_t)r * (NKV * HD) + c);
            float* vd = &Vs[r * QS_STRIDE + c];
            vd[0] = vv4.x; vd[1] = vv4.y; vd[2] = vv4.z; vd[3] = vv4.w;
        }
        __syncthreads();

        float s[4][4];
#pragma unroll
        for (int i = 0; i < 4; i++)
#pragma unroll
            for (int j = 0; j < 4; j++) s[i][j] = 0.0f;

        for (int d = 0; d < HD; d += 4) {
            float4 qv[4], kv[4];
#pragma unroll
            for (int i = 0; i < 4; i++)
                qv[i] = *(const float4*)&Qs[(4 * ty + i) * QS_STRIDE + d];
#pragma unroll
            for (int j = 0; j < 4; j++)
                kv[j] = *(const float4*)&Ks[(4 * tx + j) * QS_STRIDE + d];
#pragma unroll
            for (int i = 0; i < 4; i++)
#pragma unroll
                for (int j = 0; j < 4; j++) {
                    s[i][j] = fmaf(qv[i].x, kv[j].x, s[i][j]);
                    s[i][j] = fmaf(qv[i].y, kv[j].y, s[i][j]);
                    s[i][j] = fmaf(qv[i].z, kv[j].z, s[i][j]);
                    s[i][j] = fmaf(qv[i].w, kv[j].w, s[i][j]);
                }
        }

        const bool diag = (kb == qb);
#pragma unroll
        for (int i = 0; i < 4; i++) {
#pragma unroll
            for (int j = 0; j < 4; j++) {
                s[i][j] *= scale;
                if (diag && (4 * tx + j > 4 * ty + i)) s[i][j] = -INFINITY;
            }
        }

#pragma unroll
        for (int i = 0; i < 4; i++) {
            float rm = fmaxf(fmaxf(s[i][0], s[i][1]), fmaxf(s[i][2], s[i][3]));
#pragma unroll
            for (int o = 8; o; o >>= 1)
                rm = fmaxf(rm, __shfl_xor_sync(0xffffffffu, rm, o));
            float mnew = fmaxf(m_i[i], rm);
            float corr = __expf(m_i[i] - mnew);
            float rs = 0.0f;
#pragma unroll
            for (int j = 0; j < 4; j++) {
                s[i][j] = __expf(s[i][j] - mnew);
                rs += s[i][j];
            }
#pragma unroll
            for (int o = 8; o; o >>= 1)
                rs += __shfl_xor_sync(0xffffffffu, rs, o);
            l_i[i] = l_i[i] * corr + rs;
            m_i[i] = mnew;
#pragma unroll
            for (int j = 0; j < 8; j++) acc[i][j] *= corr;
#pragma unroll
            for (int j = 0; j < 4; j++)
                Ps[(4 * ty + i) * PS_STRIDE + 4 * tx + j] = s[i][j];
        }
        __syncthreads();

#pragma unroll 4
        for (int kk = 0; kk < 64; kk++) {
            float4 v0 = *(const float4*)&Vs[kk * QS_STRIDE + 8 * tx];
            float4 v1 = *(const float4*)&Vs[kk * QS_STRIDE + 8 * tx + 4];
#pragma unroll
            for (int i = 0; i < 4; i++) {
                float p = Ps[(4 * ty + i) * PS_STRIDE + kk];
                acc[i][0] = fmaf(p, v0.x, acc[i][0]);
                acc[i][1] = fmaf(p, v0.y, acc[i][1]);
                acc[i][2] = fmaf(p, v0.z, acc[i][2]);
                acc[i][3] = fmaf(p, v0.w, acc[i][3]);
                acc[i][4] = fmaf(p, v1.x, acc[i][4]);
                acc[i][5] = fmaf(p, v1.y, acc[i][5]);
                acc[i][6] = fmaf(p, v1.z, acc[i][6]);
                acc[i][7] = fmaf(p, v1.w, acc[i][7]);
            }
        }
    }

#pragma unroll
    for (int i = 0; i < 4; i++) {
        float inv = 1.0f / l_i[i];
        int qrow = q0 + 4 * ty + i;
        float* optr = O + (size_t)qrow * H_DIM + h * HD + 8 * tx;
        float4 c0 = make_float4(acc[i][0] * inv, acc[i][1] * inv,
                                acc[i][2] * inv, acc[i][3] * inv);
        float4 c1 = make_float4(acc[i][4] * inv, acc[i][5] * inv,
                                acc[i][6] * inv, acc[i][7] * inv);
        *(float4*)(optr) = c0;
        *(float4*)(optr + 4) = c1;
    }
}

// ---------------------------------------------------------------------------
// Launch
// Inputs (metadata order): x, sin, cos, mask, wq, wk, wv, wo, q_norm_w, k_norm_w
// ---------------------------------------------------------------------------
extern "C" void kernel_launch(void* const* d_in, const int* in_sizes, int n_in,
                              void* d_out, int out_size)
{
    const float* x    = (const float*)d_in[0];
    const float* sinp = (const float*)d_in[1];
    const float* cosp = (const float*)d_in[2];
    const float* wq   = (const float*)d_in[4];
    const float* wk   = (const float*)d_in[5];
    const float* wv   = (const float*)d_in[6];
    const float* wo   = (const float*)d_in[7];
    const float* qnw  = (const float*)d_in[8];
    const float* knw  = (const float*)d_in[9];
    float* out = (float*)d_out;

    float *qproj, *q, *kproj, *k, *v, *attn;
    cudaGetSymbolAddress((void**)&qproj, g_qproj);
    cudaGetSymbolAddress((void**)&q,     g_q);
    cudaGetSymbolAddress((void**)&kproj, g_kproj);
    cudaGetSymbolAddress((void**)&k,     g_k);
    cudaGetSymbolAddress((void**)&v,     g_v);
    cudaGetSymbolAddress((void**)&attn,  g_attn);

    // 1) projections (TF32 tensor cores)
    gemm_tf32_nt<<<dim3(H_DIM / 128, S_LEN / 128), 256>>>(x, wq, qproj, S_LEN, H_DIM, H_DIM);
    gemm_tf32_nt<<<dim3(NKV * HD / 128, S_LEN / 128), 256>>>(x, wk, kproj, S_LEN, NKV * HD, H_DIM);
    gemm_tf32_nt<<<dim3(NKV * HD / 128, S_LEN / 128), 256>>>(x, wv, v, S_LEN, NKV * HD, H_DIM);

    // 2) rmsnorm + rope
    {
        int qrows = S_LEN * NH;
        int krows = S_LEN * NKV;
        norm_rope_kernel<<<(qrows * 32 + 255) / 256, 256>>>(qproj, sinp, cosp, qnw, q, NH, qrows);
        norm_rope_kernel<<<(krows * 32 + 255) / 256, 256>>>(kproj, sinp, cosp, knw, k, NKV, krows);
    }

    // 3) causal flash attention (fp32)
    {
        size_t smem = ATTN_SMEM_FLOATS * sizeof(float);
        cudaFuncSetAttribute(attn_kernel, cudaFuncAttributeMaxDynamicSharedMemorySize, (int)smem);
        attn_kernel<<<dim3(S_LEN / 64, NH), 256, smem>>>(q, k, v, attn);
    }

    // 4) output projection (TF32 tensor cores)
    gemm_tf32_nt<<<dim3(H_DIM / 128, S_LEN / 128), 256>>>(attn, wo, out, S_LEN, H_DIM, H_DIM);
}